// round 7
// baseline (speedup 1.0000x reference)
#include <cuda_runtime.h>
#include <cuda_fp16.h>
#include <cstdint>

// LIIF render via fp16 HMMA (mma.sync m16n8k16) on sm_103.
// R7: M=128 per CTA (32 queries x 4 corners), 512 threads / 16 warps,
// warp tile 64m x 32n (warp = (wm:2) x (wn:8)); each warp owns a PRIVATE
// 32-col weight strip copy (cp.async double buffer, duplicated per wm)
// -> no per-stage __syncthreads, acc=64 regs, no spills.

namespace {

constexpr int NTHR    = 512;
constexpr int QT      = 32;
constexpr int XS_H    = 264;               // X row stride in halves (132 words)
constexpr int BW_H    = 40;                // B strip row stride in halves
constexpr int BW_BUF  = 32 * BW_H;         // halves per strip buffer
constexpr int NSTAGES = 24;                // 3 layers x 8 k-tiles of 32

__device__ __half g_wh[196608];            // w1..w3 transposed [l][n][k], fp16
__device__ float  g_proj[4 * 4096 * 256];  // P' = feat@w0f + b0 + cell-terms

__device__ __forceinline__ void cp16(uint32_t dst, const void* src) {
    asm volatile("cp.async.cg.shared.global [%0], [%1], 16;"
                 :: "r"(dst), "l"(src) : "memory");
}
__device__ __forceinline__ void cp_commit() {
    asm volatile("cp.async.commit_group;" ::: "memory");
}
template <int N>
__device__ __forceinline__ void cp_wait() {
    asm volatile("cp.async.wait_group %0;" :: "n"(N) : "memory");
}
__device__ __forceinline__ uint32_t smem_u32(const void* p) {
    uint32_t a;
    asm("{ .reg .u64 t; cvta.to.shared.u64 t, %1; cvt.u32.u64 %0, t; }"
        : "=r"(a) : "l"(p));
    return a;
}
__device__ __forceinline__ void mma_f16(float c[4], uint32_t a0, uint32_t a1,
                                        uint32_t a2, uint32_t a3,
                                        uint32_t b0, uint32_t b1) {
    asm volatile(
        "mma.sync.aligned.m16n8k16.row.col.f32.f16.f16.f32 "
        "{%0,%1,%2,%3}, {%4,%5,%6,%7}, {%8,%9}, {%0,%1,%2,%3};"
        : "+f"(c[0]), "+f"(c[1]), "+f"(c[2]), "+f"(c[3])
        : "r"(a0), "r"(a1), "r"(a2), "r"(a3), "r"(b0), "r"(b1));
}

// ---------- prep 1: w1..w3 -> fp16, transposed to [l][n][k] ----------
__global__ void prep_w_kernel(const float* __restrict__ w1, const float* __restrict__ w2,
                              const float* __restrict__ w3) {
    const int idx = blockIdx.x * blockDim.x + threadIdx.x;
    if (idx >= 196608) return;
    const int l = idx >> 16;
    const int rem = idx & 65535;
    const int nn = rem >> 8, k = rem & 255;
    const float* w = (l == 0) ? w1 : (l == 1) ? w2 : w3;
    g_wh[idx] = __float2half_rn(w[k * 256 + nn]);
}

// ---------- prep 2: P'[n][idx][c] (fp32, validated R4/R5) ----------
__global__ void prep_proj_kernel(const float* __restrict__ feat,
                                 const float* __restrict__ w0,
                                 const float* __restrict__ b0) {
    __shared__ float sf[64];
    const int blk = blockIdx.x;
    const int n   = blk >> 12;
    const int idx = blk & 4095;
    const int c   = threadIdx.x;
    if (c < 64) sf[c] = feat[((size_t)n * 64 + c) * 4096 + idx];
    __syncthreads();
    float acc = b0[c] + 0.5f * (w0[66 * 256 + c] + w0[67 * 256 + c]);
#pragma unroll 8
    for (int ch = 0; ch < 64; ch++)
        acc = fmaf(sf[ch], w0[ch * 256 + c], acc);
    g_proj[(size_t)blk * 256 + c] = acc;
}

// ---------- main kernel ----------
__global__ __launch_bounds__(NTHR, 1)
void liif_hmma_kernel(const float* __restrict__ w0, const float* __restrict__ w4,
                      const float* __restrict__ b1, const float* __restrict__ b2,
                      const float* __restrict__ b3, const float* __restrict__ b4,
                      float* __restrict__ out)
{
    extern __shared__ __half smem_h[];
    __half* Xs = smem_h;                         // 128 x 264 halves
    __half* Bs = smem_h + 128 * XS_H;            // 16 warps x 2 bufs x 1280 halves
    const uint32_t bs_u = smem_u32(Bs);

    __shared__ float s_bias[3][256];
    __shared__ float s_w0r[2][256];
    __shared__ float s_w4[772];
    __shared__ float s_b4[3];
    __shared__ int   s_idx[4][QT];
    __shared__ float s_rel[4][2][QT];
    __shared__ float s_wt[4][QT];
    __shared__ float s_red[128][4][3];

    const int tid  = threadIdx.x;
    const int wid  = tid >> 5;
    const int lane = tid & 31;
    const int g_   = lane >> 2, tig = lane & 3;
    const int wm   = wid & 1;                    // row group: rows wm*64..+63
    const int wn   = wid >> 1;                   // col strip: cols wn*32..+31
    const int n    = blockIdx.y;
    const int q0   = blockIdx.x * QT;

    // per-warp B strip copy: stage st -> buffer buf (warp-private copy)
    auto prefetch = [&](int buf, int st) {
        const int l2 = st >> 3, t2 = st & 7;
        const uint32_t dst0 = bs_u + (uint32_t)(wid * 2 * BW_BUF + buf * BW_BUF) * 2u;
#pragma unroll
        for (int j = 0; j < 4; j++) {
            const int e = lane + 32 * j;
            const int row = e >> 2, ch = e & 3;          // n-row 0..31, 16B chunk
            const __half* src = g_wh + (((l2 * 256 + wn * 32 + row) << 8) + t2 * 32 + ch * 8);
            cp16(dst0 + (uint32_t)(row * BW_H + ch * 8) * 2u, src);
        }
        cp_commit();
    };

    prefetch(0, 0);     // stage 0 in flight during setup

    for (int i = tid; i < 256; i += NTHR) {
        s_bias[0][i] = b1[i]; s_bias[1][i] = b2[i]; s_bias[2][i] = b3[i];
        s_w0r[0][i] = w0[64 * 256 + i]; s_w0r[1][i] = w0[65 * 256 + i];
    }
    if (tid < 512) { if (tid < 3) s_b4[tid] = b4[tid]; }
    for (int i = tid; i < 768; i += NTHR) s_w4[i] = w4[i];

    // per-query geometry (validated R1/R3)
    if (tid < QT) {
        const int q = q0 + tid;
        const int yq = q >> 8, xq = q & 255;
        const float c0 = (2.f * (float)yq + 1.f) * (1.f / 256.f) - 1.f;
        const float c1 = (2.f * (float)xq + 1.f) * (1.f / 256.f) - 1.f;
        const float lo = (float)(-1.0 + 1e-6), hi = (float)(1.0 - 1e-6);
        float areas[4];
#pragma unroll
        for (int t = 0; t < 4; t++) {
            const double vx = (t < 2) ? -1.0 : 1.0;
            const double vy = (t & 1) ? 1.0 : -1.0;
            const float shx = (float)(vx * (1.0 / 64.0) + 1e-6);
            const float shy = (float)(vy * (1.0 / 64.0) + 1e-6);
            const float cc0 = fminf(fmaxf(c0 + shx, lo), hi);
            const float cc1 = fminf(fmaxf(c1 + shy, lo), hi);
            int iy = (int)rintf(((cc0 + 1.f) * 64.f - 1.f) * 0.5f);
            int ix = (int)rintf(((cc1 + 1.f) * 64.f - 1.f) * 0.5f);
            iy = min(max(iy, 0), 63); ix = min(max(ix, 0), 63);
            const float qc0 = (2.f * (float)iy + 1.f) * (1.f / 64.f) - 1.f;
            const float qc1 = (2.f * (float)ix + 1.f) * (1.f / 64.f) - 1.f;
            const float r0 = (c0 - qc0) * 64.f;
            const float r1 = (c1 - qc1) * 64.f;
            s_idx[t][tid] = iy * 64 + ix;
            s_rel[t][0][tid] = r0; s_rel[t][1][tid] = r1;
            areas[t] = fabsf(r0 * r1) + 1e-9f;
        }
        const float tot = areas[0] + areas[1] + areas[2] + areas[3];
#pragma unroll
        for (int t = 0; t < 4; t++) s_wt[t][tid] = areas[3 - t] / tot;
    }
    __syncthreads();

    // h0 build: thread = (row, 64-col quarter); fp32 math, round to fp16
    {
        const int row = tid >> 2, qu = tid & 3;          // row 0..127
        const int t = row >> 5, i = row & 31;
        const int idx = s_idx[t][i];
        const float r0 = s_rel[t][0][i], r1 = s_rel[t][1][i];
        const float4* pp = (const float4*)(g_proj + (((size_t)n << 12) + idx) * 256)
                           + qu * 16;
        __half2* xw = (__half2*)Xs + row * 132 + qu * 32;
#pragma unroll
        for (int j = 0; j < 16; j++) {
            const float4 p = pp[j];
            const int c = qu * 64 + j * 4;
            const float v0 = fmaf(r0, s_w0r[0][c],     fmaf(r1, s_w0r[1][c],     p.x));
            const float v1 = fmaf(r0, s_w0r[0][c + 1], fmaf(r1, s_w0r[1][c + 1], p.y));
            const float v2 = fmaf(r0, s_w0r[0][c + 2], fmaf(r1, s_w0r[1][c + 2], p.z));
            const float v3 = fmaf(r0, s_w0r[0][c + 3], fmaf(r1, s_w0r[1][c + 3], p.w));
            xw[j * 2]     = __floats2half2_rn(fmaxf(v0, 0.f), fmaxf(v1, 0.f));
            xw[j * 2 + 1] = __floats2half2_rn(fmaxf(v2, 0.f), fmaxf(v3, 0.f));
        }
    }
    __syncthreads();

    const uint32_t* Xw = (const uint32_t*)Xs;            // half2 word view
    const uint32_t* Bw = (const uint32_t*)(Bs + wid * 2 * BW_BUF);

    float acc[4][4][4];
#pragma unroll
    for (int mt = 0; mt < 4; mt++)
#pragma unroll
        for (int nt = 0; nt < 4; nt++)
#pragma unroll
            for (int r = 0; r < 4; r++) acc[mt][nt][r] = 0.f;

    int buf = 0;
#pragma unroll 1
    for (int st = 0; st < NSTAGES; st++) {
        const int tile = st & 7;

        if (st + 1 < NSTAGES) { prefetch(buf ^ 1, st + 1); cp_wait<1>(); }
        else                  { cp_wait<0>(); }
        // no __syncthreads: B strips are warp-private, Xs is read-only here

        const uint32_t* Bb = Bw + buf * (BW_BUF / 2);
        const int kw0 = tile * 16;

#pragma unroll
        for (int s = 0; s < 2; s++) {            // two k16 steps per 32-k tile
            uint32_t b0[4], b1[4];
#pragma unroll
            for (int nt = 0; nt < 4; nt++) {
                const int bw = (nt * 8 + g_) * 20 + s * 8 + tig;
                b0[nt] = Bb[bw];
                b1[nt] = Bb[bw + 4];
            }
            const int kw = kw0 + s * 8 + tig;
#pragma unroll
            for (int mt = 0; mt < 4; mt++) {
                const int r0w = (wm * 64 + mt * 16 + g_) * 132 + kw;
                const uint32_t a0 = Xw[r0w];
                const uint32_t a1 = Xw[r0w + 8 * 132];
                const uint32_t a2 = Xw[r0w + 4];
                const uint32_t a3 = Xw[r0w + 8 * 132 + 4];
#pragma unroll
                for (int nt = 0; nt < 4; nt++)
                    mma_f16(acc[mt][nt], a0, a1, a2, a3, b0[nt], b1[nt]);
            }
        }
        buf ^= 1;

        if (tile == 7) {                         // layer boundary
            const int le = st >> 3;
            __syncthreads();                     // all reads of Xs done
#pragma unroll
            for (int mt = 0; mt < 4; mt++) {
#pragma unroll
                for (int nt = 0; nt < 4; nt++) {
                    const int c = wn * 32 + nt * 8 + 2 * tig;
                    const float bv0 = s_bias[le][c], bv1 = s_bias[le][c + 1];
                    const float v00 = fmaxf(acc[mt][nt][0] + bv0, 0.f);
                    const float v01 = fmaxf(acc[mt][nt][1] + bv1, 0.f);
                    const float v10 = fmaxf(acc[mt][nt][2] + bv0, 0.f);
                    const float v11 = fmaxf(acc[mt][nt][3] + bv1, 0.f);
                    const int r0 = wm * 64 + mt * 16 + g_;
                    __half2* xw = (__half2*)Xs;
                    xw[r0 * 132 + wn * 16 + nt * 4 + tig]       = __floats2half2_rn(v00, v01);
                    xw[(r0 + 8) * 132 + wn * 16 + nt * 4 + tig] = __floats2half2_rn(v10, v11);
                    acc[mt][nt][0] = 0.f; acc[mt][nt][1] = 0.f;
                    acc[mt][nt][2] = 0.f; acc[mt][nt][3] = 0.f;
                }
            }
            __syncthreads();                     // writes visible before next layer
        }
    }

    // final 256->3 layer, fp32: thread = (row, 64-k quarter)
    {
        const int row = tid >> 2, qu = tid & 3;
        const __half2* xw = (const __half2*)Xs + row * 132 + qu * 32;
        float a0 = 0.f, a1 = 0.f, a2 = 0.f;
#pragma unroll 16
        for (int j = 0; j < 32; j++) {
            const float2 y = __half22float2(xw[j]);
            const float* wr = &s_w4[(qu * 64 + 2 * j) * 3];
            a0 = fmaf(y.x, wr[0], fmaf(y.y, wr[3], a0));
            a1 = fmaf(y.x, wr[1], fmaf(y.y, wr[4], a1));
            a2 = fmaf(y.x, wr[2], fmaf(y.y, wr[5], a2));
        }
        s_red[row][qu][0] = a0; s_red[row][qu][1] = a1; s_red[row][qu][2] = a2;
    }
    __syncthreads();

    // area-weighted combine + NCHW write
    if (tid < 96) {
        const int i = tid / 3;
        const int o = tid - 3 * (tid / 3);
        float v = 0.f;
#pragma unroll
        for (int t = 0; t < 4; t++) {
            const int row = t * QT + i;
            const float p = s_b4[o] + s_red[row][0][o] + s_red[row][1][o]
                          + s_red[row][2][o] + s_red[row][3][o];
            v += s_wt[t][i] * p;
        }
        out[((size_t)n * 3 + o) * 65536 + q0 + i] = v;
    }
}

} // anonymous namespace

extern "C" void kernel_launch(void* const* d_in, const int* in_sizes, int n_in,
                              void* d_out, int out_size)
{
    (void)in_sizes; (void)n_in; (void)out_size;
    const float* feat = (const float*)d_in[0];
    const float* w0 = (const float*)d_in[1];
    const float* b0 = (const float*)d_in[2];
    const float* w1 = (const float*)d_in[3];
    const float* b1 = (const float*)d_in[4];
    const float* w2 = (const float*)d_in[5];
    const float* b2 = (const float*)d_in[6];
    const float* w3 = (const float*)d_in[7];
    const float* b3 = (const float*)d_in[8];
    const float* w4 = (const float*)d_in[9];
    const float* b4 = (const float*)d_in[10];

    prep_w_kernel<<<(196608 + 255) / 256, 256>>>(w1, w2, w3);
    prep_proj_kernel<<<16384, 256>>>(feat, w0, b0);

    const size_t shmem = (size_t)(128 * XS_H + 16 * 2 * BW_BUF) * sizeof(__half); // 149504 B
    cudaFuncSetAttribute(liif_hmma_kernel,
                         cudaFuncAttributeMaxDynamicSharedMemorySize, (int)shmem);
    dim3 grid(65536 / QT, 4);
    liif_hmma_kernel<<<grid, NTHR, shmem>>>(w0, w4, b1, b2, b3, b4, (float*)d_out);
}

// round 8
// speedup vs baseline: 1.5300x; 1.5300x over previous
#include <cuda_runtime.h>
#include <cuda_fp16.h>
#include <cstdint>

// LIIF render via fp16 HMMA (mma.sync m16n8k16) on sm_103.
// R8 = R5 (best: 1559us) + k-tile 64 (12 stages) + ldmatrix.x4 A-fragments.
// M=128 per CTA (32 queries x 4 corners), 256 threads / 8 warps,
// warp tile 128m x 32n; warp-private B strips, cp.async double buffer,
// no per-stage __syncthreads. Layer-0 folded into precomputed projection P'.

namespace {

constexpr int NTHR    = 256;
constexpr int QT      = 32;
constexpr int XS_H    = 264;               // X row stride in halves (132 words)
constexpr int BW_H    = 72;                // B strip row stride in halves (36 words)
constexpr int BW_BUF  = 32 * BW_H;         // halves per strip buffer (2304)
constexpr int NSTAGES = 12;                // 3 layers x 4 k-tiles of 64

__device__ __half g_wh[196608];            // w1..w3 transposed [l][n][k], fp16
__device__ float  g_proj[4 * 4096 * 256];  // P' = feat@w0f + b0 + cell-terms

__device__ __forceinline__ void cp16(uint32_t dst, const void* src) {
    asm volatile("cp.async.cg.shared.global [%0], [%1], 16;"
                 :: "r"(dst), "l"(src) : "memory");
}
__device__ __forceinline__ void cp_commit() {
    asm volatile("cp.async.commit_group;" ::: "memory");
}
template <int N>
__device__ __forceinline__ void cp_wait() {
    asm volatile("cp.async.wait_group %0;" :: "n"(N) : "memory");
}
__device__ __forceinline__ uint32_t smem_u32(const void* p) {
    uint32_t a;
    asm("{ .reg .u64 t; cvta.to.shared.u64 t, %1; cvt.u32.u64 %0, t; }"
        : "=r"(a) : "l"(p));
    return a;
}
__device__ __forceinline__ void ldsm4(uint32_t& r0, uint32_t& r1,
                                      uint32_t& r2, uint32_t& r3, uint32_t addr) {
    asm volatile("ldmatrix.sync.aligned.m8n8.x4.shared.b16 {%0,%1,%2,%3}, [%4];"
                 : "=r"(r0), "=r"(r1), "=r"(r2), "=r"(r3) : "r"(addr));
}
__device__ __forceinline__ void mma_f16(float c[4], uint32_t a0, uint32_t a1,
                                        uint32_t a2, uint32_t a3,
                                        uint32_t b0, uint32_t b1) {
    asm volatile(
        "mma.sync.aligned.m16n8k16.row.col.f32.f16.f16.f32 "
        "{%0,%1,%2,%3}, {%4,%5,%6,%7}, {%8,%9}, {%0,%1,%2,%3};"
        : "+f"(c[0]), "+f"(c[1]), "+f"(c[2]), "+f"(c[3])
        : "r"(a0), "r"(a1), "r"(a2), "r"(a3), "r"(b0), "r"(b1));
}

// ---------- prep 1: w1..w3 -> fp16, transposed to [l][n][k] ----------
__global__ void prep_w_kernel(const float* __restrict__ w1, const float* __restrict__ w2,
                              const float* __restrict__ w3) {
    const int idx = blockIdx.x * blockDim.x + threadIdx.x;
    if (idx >= 196608) return;
    const int l = idx >> 16;
    const int rem = idx & 65535;
    const int nn = rem >> 8, k = rem & 255;
    const float* w = (l == 0) ? w1 : (l == 1) ? w2 : w3;
    g_wh[idx] = __float2half_rn(w[k * 256 + nn]);
}

// ---------- prep 2: P'[n][idx][c] (fp32, validated R4/R5) ----------
__global__ void prep_proj_kernel(const float* __restrict__ feat,
                                 const float* __restrict__ w0,
                                 const float* __restrict__ b0) {
    __shared__ float sf[64];
    const int blk = blockIdx.x;
    const int n   = blk >> 12;
    const int idx = blk & 4095;
    const int c   = threadIdx.x;
    if (c < 64) sf[c] = feat[((size_t)n * 64 + c) * 4096 + idx];
    __syncthreads();
    float acc = b0[c] + 0.5f * (w0[66 * 256 + c] + w0[67 * 256 + c]);
#pragma unroll 8
    for (int ch = 0; ch < 64; ch++)
        acc = fmaf(sf[ch], w0[ch * 256 + c], acc);
    g_proj[(size_t)blk * 256 + c] = acc;
}

// ---------- main kernel ----------
__global__ __launch_bounds__(NTHR, 1)
void liif_hmma_kernel(const float* __restrict__ w0, const float* __restrict__ w4,
                      const float* __restrict__ b1, const float* __restrict__ b2,
                      const float* __restrict__ b3, const float* __restrict__ b4,
                      float* __restrict__ out)
{
    extern __shared__ __half smem_h[];
    __half* Xs = smem_h;                         // 128 x 264 halves
    __half* Bs = smem_h + 128 * XS_H;            // 8 warps x 2 bufs x 2304 halves
    const uint32_t xs_u = smem_u32(Xs);
    const uint32_t bs_u = smem_u32(Bs);

    __shared__ float s_bias[3][256];
    __shared__ float s_w0r[2][256];
    __shared__ float s_w4[772];
    __shared__ float s_b4[3];
    __shared__ int   s_idx[4][QT];
    __shared__ float s_rel[4][2][QT];
    __shared__ float s_wt[4][QT];
    __shared__ float s_red[128][2][3];

    const int tid  = threadIdx.x;
    const int wid  = tid >> 5;
    const int lane = tid & 31;
    const int g_   = lane >> 2, tig = lane & 3;
    const int n    = blockIdx.y;
    const int q0   = blockIdx.x * QT;

    // per-warp B strip copy: stage st (layer st>>2, tile st&3) -> buffer buf
    auto prefetch = [&](int buf, int st) {
        const int l2 = st >> 2, t2 = st & 3;
        const uint32_t dst0 = bs_u + (uint32_t)(wid * 2 * BW_BUF + buf * BW_BUF) * 2u;
#pragma unroll
        for (int j = 0; j < 8; j++) {
            const int e = lane + 32 * j;
            const int row = e >> 3, ch = e & 7;          // n-row 0..31, 16B chunk 0..7
            const __half* src = g_wh + (((l2 * 256 + wid * 32 + row) << 8) + t2 * 64 + ch * 8);
            cp16(dst0 + (uint32_t)(row * BW_H + ch * 8) * 2u, src);
        }
        cp_commit();
    };

    prefetch(0, 0);     // stage 0 in flight during setup

    for (int i = tid; i < 256; i += NTHR) {
        s_bias[0][i] = b1[i]; s_bias[1][i] = b2[i]; s_bias[2][i] = b3[i];
        s_w0r[0][i] = w0[64 * 256 + i]; s_w0r[1][i] = w0[65 * 256 + i];
    }
    for (int i = tid; i < 768; i += NTHR) s_w4[i] = w4[i];
    if (tid < 3) s_b4[tid] = b4[tid];

    // per-query geometry (validated R1/R3)
    if (tid < QT) {
        const int q = q0 + tid;
        const int yq = q >> 8, xq = q & 255;
        const float c0 = (2.f * (float)yq + 1.f) * (1.f / 256.f) - 1.f;
        const float c1 = (2.f * (float)xq + 1.f) * (1.f / 256.f) - 1.f;
        const float lo = (float)(-1.0 + 1e-6), hi = (float)(1.0 - 1e-6);
        float areas[4];
#pragma unroll
        for (int t = 0; t < 4; t++) {
            const double vx = (t < 2) ? -1.0 : 1.0;
            const double vy = (t & 1) ? 1.0 : -1.0;
            const float shx = (float)(vx * (1.0 / 64.0) + 1e-6);
            const float shy = (float)(vy * (1.0 / 64.0) + 1e-6);
            const float cc0 = fminf(fmaxf(c0 + shx, lo), hi);
            const float cc1 = fminf(fmaxf(c1 + shy, lo), hi);
            int iy = (int)rintf(((cc0 + 1.f) * 64.f - 1.f) * 0.5f);
            int ix = (int)rintf(((cc1 + 1.f) * 64.f - 1.f) * 0.5f);
            iy = min(max(iy, 0), 63); ix = min(max(ix, 0), 63);
            const float qc0 = (2.f * (float)iy + 1.f) * (1.f / 64.f) - 1.f;
            const float qc1 = (2.f * (float)ix + 1.f) * (1.f / 64.f) - 1.f;
            const float r0 = (c0 - qc0) * 64.f;
            const float r1 = (c1 - qc1) * 64.f;
            s_idx[t][tid] = iy * 64 + ix;
            s_rel[t][0][tid] = r0; s_rel[t][1][tid] = r1;
            areas[t] = fabsf(r0 * r1) + 1e-9f;
        }
        const float tot = areas[0] + areas[1] + areas[2] + areas[3];
#pragma unroll
        for (int t = 0; t < 4; t++) s_wt[t][tid] = areas[3 - t] / tot;
    }
    __syncthreads();

    // h0 build: thread = (row, 128-col half); fp32 math, round to fp16
    {
        const int row = tid >> 1, hseg = tid & 1;
        const int t = row >> 5, i = row & 31;
        const int idx = s_idx[t][i];
        const float r0 = s_rel[t][0][i], r1 = s_rel[t][1][i];
        const float4* pp = (const float4*)(g_proj + (((size_t)n << 12) + idx) * 256)
                           + hseg * 32;
        __half2* xw = (__half2*)Xs + row * 132 + hseg * 64;
#pragma unroll
        for (int j = 0; j < 32; j++) {
            const float4 p = pp[j];
            const int c = hseg * 128 + j * 4;
            const float v0 = fmaf(r0, s_w0r[0][c],     fmaf(r1, s_w0r[1][c],     p.x));
            const float v1 = fmaf(r0, s_w0r[0][c + 1], fmaf(r1, s_w0r[1][c + 1], p.y));
            const float v2 = fmaf(r0, s_w0r[0][c + 2], fmaf(r1, s_w0r[1][c + 2], p.z));
            const float v3 = fmaf(r0, s_w0r[0][c + 3], fmaf(r1, s_w0r[1][c + 3], p.w));
            xw[j * 2]     = __floats2half2_rn(fmaxf(v0, 0.f), fmaxf(v1, 0.f));
            xw[j * 2 + 1] = __floats2half2_rn(fmaxf(v2, 0.f), fmaxf(v3, 0.f));
        }
    }
    __syncthreads();

    // ldmatrix per-lane A base: row = lane&15, k-halves add = (lane>>4)*8
    const int lrow = lane & 15;
    const int kadd = (lane >> 4) << 3;
    const uint32_t a_lane = xs_u + (uint32_t)(lrow * XS_H + kadd) * 2u;

    const uint32_t* Bw = (const uint32_t*)(Bs + wid * 2 * BW_BUF);

    float acc[8][4][4];
#pragma unroll
    for (int mt = 0; mt < 8; mt++)
#pragma unroll
        for (int nt = 0; nt < 4; nt++)
#pragma unroll
            for (int r = 0; r < 4; r++) acc[mt][nt][r] = 0.f;

    int buf = 0;
#pragma unroll 1
    for (int st = 0; st < NSTAGES; st++) {
        const int tile = st & 3;

        if (st + 1 < NSTAGES) { prefetch(buf ^ 1, st + 1); cp_wait<1>(); }
        else                  { cp_wait<0>(); }
        // no __syncthreads: B strips are warp-private, Xs is read-only here

        const uint32_t* Bb = Bw + buf * (BW_BUF / 2);
        const uint32_t a_st = a_lane + (uint32_t)(tile * 64) * 2u;   // halves -> bytes

#pragma unroll
        for (int s = 0; s < 4; s++) {            // four k16 steps per 64-k tile
            uint32_t b0[4], b1[4];
#pragma unroll
            for (int nt = 0; nt < 4; nt++) {
                const int bw = (nt * 8 + g_) * 36 + s * 8 + tig;
                b0[nt] = Bb[bw];
                b1[nt] = Bb[bw + 4];
            }
            const uint32_t a_s = a_st + (uint32_t)(s * 32);
#pragma unroll
            for (int mt = 0; mt < 8; mt++) {
                uint32_t a0, a1, a2, a3;
                ldsm4(a0, a1, a2, a3, a_s + (uint32_t)(mt * 16 * XS_H * 2));
#pragma unroll
                for (int nt = 0; nt < 4; nt++)
                    mma_f16(acc[mt][nt], a0, a1, a2, a3, b0[nt], b1[nt]);
            }
        }
        buf ^= 1;

        if (tile == 3) {                         // layer boundary
            const int le = st >> 2;
            __syncthreads();                     // all reads of Xs done
#pragma unroll
            for (int mt = 0; mt < 8; mt++) {
#pragma unroll
                for (int nt = 0; nt < 4; nt++) {
                    const int c = wid * 32 + nt * 8 + 2 * tig;
                    const float bv0 = s_bias[le][c], bv1 = s_bias[le][c + 1];
                    const float v00 = fmaxf(acc[mt][nt][0] + bv0, 0.f);
                    const float v01 = fmaxf(acc[mt][nt][1] + bv1, 0.f);
                    const float v10 = fmaxf(acc[mt][nt][2] + bv0, 0.f);
                    const float v11 = fmaxf(acc[mt][nt][3] + bv1, 0.f);
                    const int r0 = mt * 16 + g_;
                    __half2* xw = (__half2*)Xs;
                    xw[r0 * 132 + wid * 16 + nt * 4 + tig]       = __floats2half2_rn(v00, v01);
                    xw[(r0 + 8) * 132 + wid * 16 + nt * 4 + tig] = __floats2half2_rn(v10, v11);
                    acc[mt][nt][0] = 0.f; acc[mt][nt][1] = 0.f;
                    acc[mt][nt][2] = 0.f; acc[mt][nt][3] = 0.f;
                }
            }
            __syncthreads();                     // writes visible before next layer
        }
    }

    // final 256->3 layer, fp32: thread = (row, k-half)
    {
        const int row = tid >> 1, hseg = tid & 1;
        const __half2* xw = (const __half2*)Xs + row * 132 + hseg * 64;
        float a0 = 0.f, a1 = 0.f, a2 = 0.f;
#pragma unroll 16
        for (int j = 0; j < 64; j++) {
            const float2 y = __half22float2(xw[j]);
            const float* wr = &s_w4[(hseg * 128 + 2 * j) * 3];
            a0 = fmaf(y.x, wr[0], fmaf(y.y, wr[3], a0));
            a1 = fmaf(y.x, wr[1], fmaf(y.y, wr[4], a1));
            a2 = fmaf(y.x, wr[2], fmaf(y.y, wr[5], a2));
        }
        s_red[row][hseg][0] = a0; s_red[row][hseg][1] = a1; s_red[row][hseg][2] = a2;
    }
    __syncthreads();

    // area-weighted combine + NCHW write
    if (tid < 96) {
        const int i = tid / 3;
        const int o = tid - 3 * (tid / 3);
        float v = 0.f;
#pragma unroll
        for (int t = 0; t < 4; t++) {
            const int row = t * 32 + i;
            const float p = s_b4[o] + s_red[row][0][o] + s_red[row][1][o];
            v += s_wt[t][i] * p;
        }
        out[((size_t)n * 3 + o) * 65536 + q0 + i] = v;
    }
}

} // anonymous namespace

extern "C" void kernel_launch(void* const* d_in, const int* in_sizes, int n_in,
                              void* d_out, int out_size)
{
    (void)in_sizes; (void)n_in; (void)out_size;
    const float* feat = (const float*)d_in[0];
    const float* w0 = (const float*)d_in[1];
    const float* b0 = (const float*)d_in[2];
    const float* w1 = (const float*)d_in[3];
    const float* b1 = (const float*)d_in[4];
    const float* w2 = (const float*)d_in[5];
    const float* b2 = (const float*)d_in[6];
    const float* w3 = (const float*)d_in[7];
    const float* b3 = (const float*)d_in[8];
    const float* w4 = (const float*)d_in[9];
    const float* b4 = (const float*)d_in[10];

    prep_w_kernel<<<(196608 + 255) / 256, 256>>>(w1, w2, w3);
    prep_proj_kernel<<<16384, 256>>>(feat, w0, b0);

    const size_t shmem = (size_t)(128 * XS_H + 8 * 2 * BW_BUF) * sizeof(__half); // 141312 B
    cudaFuncSetAttribute(liif_hmma_kernel,
                         cudaFuncAttributeMaxDynamicSharedMemorySize, (int)shmem);
    dim3 grid(65536 / QT, 4);
    liif_hmma_kernel<<<grid, NTHR, shmem>>>(w0, w4, b1, b2, b3, b4, (float*)d_out);
}